// round 2
// baseline (speedup 1.0000x reference)
#include <cuda_runtime.h>
#include <math.h>

#define BATCH 2
#define CH    256
#define NPIX  4096     // 64*64
#define NGRP  32
#define CPG   (CH/NGRP)  // 8
#define GN_EPS 1e-6f
#define QSCALE 0.0625f   // 256^-0.5

// ---------------- scratch (static device globals; no allocation) ----------------
__device__ float g_h[BATCH*CH*NPIX];                 // normalized input  (b,c,n)
__device__ float g_q[BATCH*CH*NPIX];                 // q (scaled)        (b,c,n)
__device__ float g_k[BATCH*CH*NPIX];
__device__ float g_v[BATCH*CH*NPIX];
__device__ float g_o[BATCH*CH*NPIX];                 // attn output       (b,c,n)
__device__ float g_s[(size_t)BATCH*NPIX*NPIX];       // scores/attn (b,i,j) 128 MiB

// ---------------- GroupNorm: one block per (batch, group) ----------------
__global__ void groupnorm_kernel(const float* __restrict__ x,
                                 const float* __restrict__ gamma,
                                 const float* __restrict__ beta) {
    int bg = blockIdx.x;
    int b  = bg / NGRP;
    int g  = bg % NGRP;
    const size_t base = ((size_t)b*CH + (size_t)g*CPG) * NPIX;
    const float* xp = x   + base;
    float*       hp = g_h + base;
    const int tid = threadIdx.x;      // 256 threads
    const int NEL = CPG*NPIX;         // 32768

    float s = 0.f, s2 = 0.f;
    for (int i = tid; i < NEL; i += 256) {
        float v = xp[i];
        s += v; s2 += v*v;
    }
    __shared__ float sh[256], sh2[256];
    sh[tid] = s; sh2[tid] = s2;
    __syncthreads();
    for (int o = 128; o > 0; o >>= 1) {
        if (tid < o) { sh[tid] += sh[tid+o]; sh2[tid] += sh2[tid+o]; }
        __syncthreads();
    }
    float inv_n = 1.0f / (float)NEL;
    float mean  = sh[0] * inv_n;
    float var   = sh2[0] * inv_n - mean*mean;
    float rstd  = rsqrtf(var + GN_EPS);

    for (int i = tid; i < NEL; i += 256) {
        int ch = g*CPG + i / NPIX;
        hp[i] = (xp[i] - mean) * rstd * gamma[ch] + beta[ch];
    }
}

// ---------------- GEMM: Out[b,o,n] = (sum_c W[o,c]*Bm[b,c,n] + bias[o])*scale (+resid)
// M=256 (o), N=4096 (n), K=256 (c). BM=BN=64, BK=16, 256 thr, 4x4/thread.
template<bool RESID>
__global__ void gemm_wh(const float* __restrict__ W,
                        const float* __restrict__ bias,
                        const float* __restrict__ Bm,
                        float* __restrict__ Outp,
                        const float* __restrict__ Rm,
                        float scale) {
    const int b  = blockIdx.z;
    const float* Bp = Bm + (size_t)b*CH*NPIX;
    float*       Op = Outp + (size_t)b*CH*NPIX;
    const float* Rp = RESID ? (Rm + (size_t)b*CH*NPIX) : nullptr;

    const int m0 = blockIdx.y * 64;
    const int n0 = blockIdx.x * 64;
    const int tid = threadIdx.x;
    const int tx = tid & 15, ty = tid >> 4;

    __shared__ float As[16][65];   // [k][m]
    __shared__ float Bs[16][65];   // [k][n]

    float acc[4][4];
    #pragma unroll
    for (int i = 0; i < 4; i++)
        #pragma unroll
        for (int j = 0; j < 4; j++) acc[i][j] = 0.f;

    const int a_kk = tid & 15;        // A load: kk = tid%16, mm = tid/16 (+16s)
    const int a_mm = tid >> 4;
    const int b_nn = tid & 63;        // B load: nn = tid%64, kk = tid/64 (+4s)
    const int b_kk = tid >> 6;

    for (int k0 = 0; k0 < CH; k0 += 16) {
        #pragma unroll
        for (int s = 0; s < 4; s++) {
            int mm = a_mm + 16*s;
            As[a_kk][mm] = W[(size_t)(m0 + mm)*CH + k0 + a_kk];
        }
        #pragma unroll
        for (int s = 0; s < 4; s++) {
            int kk = b_kk + 4*s;
            Bs[kk][b_nn] = Bp[(size_t)(k0 + kk)*NPIX + n0 + b_nn];
        }
        __syncthreads();
        #pragma unroll
        for (int kk = 0; kk < 16; kk++) {
            float a[4], bb[4];
            #pragma unroll
            for (int i = 0; i < 4; i++) a[i]  = As[kk][ty*4 + i];
            #pragma unroll
            for (int j = 0; j < 4; j++) bb[j] = Bs[kk][tx*4 + j];
            #pragma unroll
            for (int i = 0; i < 4; i++)
                #pragma unroll
                for (int j = 0; j < 4; j++) acc[i][j] += a[i]*bb[j];
        }
        __syncthreads();
    }

    #pragma unroll
    for (int i = 0; i < 4; i++) {
        int m = m0 + ty*4 + i;
        float bv = bias[m];
        #pragma unroll
        for (int j = 0; j < 4; j++) {
            int n = n0 + tx*4 + j;
            float v = (acc[i][j] + bv) * scale;
            if (RESID) v += Rp[(size_t)m*NPIX + n];
            Op[(size_t)m*NPIX + n] = v;
        }
    }
}

// ---------------- scores: S[b,i,j] = sum_c q[b,c,i]*k[b,c,j]  (q pre-scaled)
// M=N=4096, K=256. Both operands K-major (TN form).
__global__ void gemm_scores() {
    const int b = blockIdx.z;
    const float* Qp = g_q + (size_t)b*CH*NPIX;
    const float* Kp = g_k + (size_t)b*CH*NPIX;
    float*       Sp = g_s + (size_t)b*NPIX*NPIX;

    const int i0 = blockIdx.y * 64;
    const int j0 = blockIdx.x * 64;
    const int tid = threadIdx.x;
    const int tx = tid & 15, ty = tid >> 4;

    __shared__ float As[16][65];   // [k][i]
    __shared__ float Bs[16][65];   // [k][j]

    float acc[4][4];
    #pragma unroll
    for (int i = 0; i < 4; i++)
        #pragma unroll
        for (int j = 0; j < 4; j++) acc[i][j] = 0.f;

    const int l_mm = tid & 63;     // column within tile (coalesced)
    const int l_kk = tid >> 6;     // row (+4s)

    for (int k0 = 0; k0 < CH; k0 += 16) {
        #pragma unroll
        for (int s = 0; s < 4; s++) {
            int kk = l_kk + 4*s;
            As[kk][l_mm] = Qp[(size_t)(k0 + kk)*NPIX + i0 + l_mm];
            Bs[kk][l_mm] = Kp[(size_t)(k0 + kk)*NPIX + j0 + l_mm];
        }
        __syncthreads();
        #pragma unroll
        for (int kk = 0; kk < 16; kk++) {
            float a[4], bb[4];
            #pragma unroll
            for (int i = 0; i < 4; i++) a[i]  = As[kk][ty*4 + i];
            #pragma unroll
            for (int j = 0; j < 4; j++) bb[j] = Bs[kk][tx*4 + j];
            #pragma unroll
            for (int i = 0; i < 4; i++)
                #pragma unroll
                for (int j = 0; j < 4; j++) acc[i][j] += a[i]*bb[j];
        }
        __syncthreads();
    }

    #pragma unroll
    for (int i = 0; i < 4; i++) {
        size_t row = (size_t)(i0 + ty*4 + i) * NPIX;
        #pragma unroll
        for (int j = 0; j < 4; j++)
            Sp[row + j0 + tx*4 + j] = acc[i][j];
    }
}

// ---------------- softmax over last dim (row length 4096), in-place on g_s ----
__global__ void softmax_kernel() {
    const size_t row = (size_t)blockIdx.x;     // 0 .. BATCH*NPIX-1
    float* p = g_s + row * NPIX;
    const int tid = threadIdx.x;               // 256

    float v[16];
    float mx = -INFINITY;
    #pragma unroll
    for (int s = 0; s < 16; s++) {
        v[s] = p[tid + 256*s];
        mx = fmaxf(mx, v[s]);
    }
    __shared__ float sh[256];
    sh[tid] = mx; __syncthreads();
    for (int o = 128; o > 0; o >>= 1) {
        if (tid < o) sh[tid] = fmaxf(sh[tid], sh[tid+o]);
        __syncthreads();
    }
    mx = sh[0];
    __syncthreads();

    float sum = 0.f;
    #pragma unroll
    for (int s = 0; s < 16; s++) {
        v[s] = __expf(v[s] - mx);
        sum += v[s];
    }
    sh[tid] = sum; __syncthreads();
    for (int o = 128; o > 0; o >>= 1) {
        if (tid < o) sh[tid] += sh[tid+o];
        __syncthreads();
    }
    float inv = 1.0f / sh[0];
    #pragma unroll
    for (int s = 0; s < 16; s++)
        p[tid + 256*s] = v[s] * inv;
}

// ---------------- PV: o[b,c,i] = sum_j v[b,c,j] * attn[b,i,j]  (NT form)
// M=256 (c), N=4096 (i), K=4096 (j).
__global__ void gemm_pv() {
    const int b = blockIdx.z;
    const float* Vp = g_v + (size_t)b*CH*NPIX;
    const float* Pp = g_s + (size_t)b*NPIX*NPIX;
    float*       Op = g_o + (size_t)b*CH*NPIX;

    const int m0 = blockIdx.y * 64;   // c
    const int n0 = blockIdx.x * 64;   // i
    const int tid = threadIdx.x;
    const int tx = tid & 15, ty = tid >> 4;

    __shared__ float As[16][65];   // [k][m]  (V transposed on store)
    __shared__ float Bs[16][65];   // [k][n]  (P transposed on store)

    float acc[4][4];
    #pragma unroll
    for (int i = 0; i < 4; i++)
        #pragma unroll
        for (int j = 0; j < 4; j++) acc[i][j] = 0.f;

    const int l_kk = tid & 15;     // contiguous k within a row (coalesced global)
    const int l_mm = tid >> 4;     // row (+16s)

    for (int k0 = 0; k0 < NPIX; k0 += 16) {
        #pragma unroll
        for (int s = 0; s < 4; s++) {
            int mm = l_mm + 16*s;
            As[l_kk][mm] = Vp[(size_t)(m0 + mm)*NPIX + k0 + l_kk];
            Bs[l_kk][mm] = Pp[(size_t)(n0 + mm)*NPIX + k0 + l_kk];
        }
        __syncthreads();
        #pragma unroll
        for (int kk = 0; kk < 16; kk++) {
            float a[4], bb[4];
            #pragma unroll
            for (int i = 0; i < 4; i++) a[i]  = As[kk][ty*4 + i];
            #pragma unroll
            for (int j = 0; j < 4; j++) bb[j] = Bs[kk][tx*4 + j];
            #pragma unroll
            for (int i = 0; i < 4; i++)
                #pragma unroll
                for (int j = 0; j < 4; j++) acc[i][j] += a[i]*bb[j];
        }
        __syncthreads();
    }

    #pragma unroll
    for (int i = 0; i < 4; i++) {
        size_t row = (size_t)(m0 + ty*4 + i) * NPIX;
        #pragma unroll
        for (int j = 0; j < 4; j++)
            Op[row + n0 + tx*4 + j] = acc[i][j];
    }
}

// ---------------- launch ----------------
extern "C" void kernel_launch(void* const* d_in, const int* in_sizes, int n_in,
                              void* d_out, int out_size) {
    const float* x     = (const float*)d_in[0];
    const float* gamma = (const float*)d_in[1];
    const float* beta  = (const float*)d_in[2];
    const float* wq = (const float*)d_in[3];
    const float* bq = (const float*)d_in[4];
    const float* wk = (const float*)d_in[5];
    const float* bk = (const float*)d_in[6];
    const float* wv = (const float*)d_in[7];
    const float* bv = (const float*)d_in[8];
    const float* wp = (const float*)d_in[9];
    const float* bp = (const float*)d_in[10];
    float* out = (float*)d_out;

    float *p_h, *p_q, *p_k, *p_v, *p_o;
    cudaGetSymbolAddress((void**)&p_h, g_h);
    cudaGetSymbolAddress((void**)&p_q, g_q);
    cudaGetSymbolAddress((void**)&p_k, g_k);
    cudaGetSymbolAddress((void**)&p_v, g_v);
    cudaGetSymbolAddress((void**)&p_o, g_o);

    // 1. GroupNorm
    groupnorm_kernel<<<BATCH*NGRP, 256>>>(x, gamma, beta);

    // 2. q/k/v 1x1 convs (q pre-scaled by C^-0.5)
    dim3 gq(NPIX/64, CH/64, BATCH);
    gemm_wh<false><<<gq, 256>>>(wq, bq, p_h, p_q, nullptr, QSCALE);
    gemm_wh<false><<<gq, 256>>>(wk, bk, p_h, p_k, nullptr, 1.0f);
    gemm_wh<false><<<gq, 256>>>(wv, bv, p_h, p_v, nullptr, 1.0f);

    // 3. scores = q^T k
    dim3 gs(NPIX/64, NPIX/64, BATCH);
    gemm_scores<<<gs, 256>>>();

    // 4. softmax over keys
    softmax_kernel<<<BATCH*NPIX, 256>>>();

    // 5. out = V . attn^T
    gemm_pv<<<gq, 256>>>();

    // 6. proj + bias + residual
    gemm_wh<true><<<gq, 256>>>(wp, bp, p_o, out, x, 1.0f);
}

// round 3
// speedup vs baseline: 1.6237x; 1.6237x over previous
#include <cuda_runtime.h>
#include <math.h>

#define BATCH 2
#define CH    256
#define NPIX  4096     // 64*64
#define NGRP  32
#define CPG   (CH/NGRP)  // 8
#define GN_EPS 1e-6f
#define QSCALE 0.0625f   // 256^-0.5

#define BM 128
#define BN 128
#define BK 8
#define SPITCH 132       // padded smem pitch: keeps LDS.128 aligned (528B rows) + bank-clean scatter

// ---------------- scratch (static device globals; no allocation) ----------------
__device__ float g_h[BATCH*CH*NPIX];                 // normalized input  (b,c,n)
__device__ float g_q[BATCH*CH*NPIX];
__device__ float g_k[BATCH*CH*NPIX];
__device__ float g_v[BATCH*CH*NPIX];
__device__ float g_o[BATCH*CH*NPIX];                 // attn output       (b,c,n)
__device__ float g_s[(size_t)BATCH*NPIX*NPIX];       // scores/attn (b,i,j) 128 MiB

// ---------------- GroupNorm: one block per (batch, group) ----------------
__global__ void groupnorm_kernel(const float* __restrict__ x,
                                 const float* __restrict__ gamma,
                                 const float* __restrict__ beta) {
    int bg = blockIdx.x;
    int b  = bg / NGRP;
    int g  = bg % NGRP;
    const size_t base = ((size_t)b*CH + (size_t)g*CPG) * NPIX;
    const float4* xp4 = (const float4*)(x   + base);
    float4*       hp4 = (float4*)      (g_h + base);
    const int tid = threadIdx.x;      // 256 threads
    const int NV = CPG*NPIX/4;        // 8192 float4

    float s = 0.f, s2 = 0.f;
    for (int i = tid; i < NV; i += 256) {
        float4 v = xp4[i];
        s  += v.x + v.y + v.z + v.w;
        s2 += v.x*v.x + v.y*v.y + v.z*v.z + v.w*v.w;
    }
    __shared__ float sh[256], sh2[256];
    sh[tid] = s; sh2[tid] = s2;
    __syncthreads();
    for (int o = 128; o > 0; o >>= 1) {
        if (tid < o) { sh[tid] += sh[tid+o]; sh2[tid] += sh2[tid+o]; }
        __syncthreads();
    }
    float inv_n = 1.0f / (float)(CPG*NPIX);
    float mean  = sh[0] * inv_n;
    float var   = sh2[0] * inv_n - mean*mean;
    float rstd  = rsqrtf(var + GN_EPS);

    for (int i = tid; i < NV; i += 256) {
        int ch = g*CPG + (i*4) / NPIX;
        float ga = gamma[ch] * rstd;
        float be = beta[ch] - mean * ga;
        float4 v = xp4[i];
        v.x = v.x*ga + be; v.y = v.y*ga + be;
        v.z = v.z*ga + be; v.w = v.w*ga + be;
        hp4[i] = v;
    }
}

// ---------------- generic 128x128x8 SGEMM ----------------
// AL: 0 = A[m*lda + k] (K-major rows), 1 = A[k*lda + m] (M contiguous)
// BL: 0 = B[k*ldb + n] (N contiguous), 1 = B[n*ldb + k] (K-major rows)
// Out[m*ldo + n] = (acc + bias[m]) * scale (+ R[m*ldo + n])
template<int AL, int BL, bool BIAS, bool RESID>
__global__ __launch_bounds__(256, 2)
void sgemm(const float* __restrict__ A, const float* __restrict__ B,
           const float* __restrict__ bias, float* __restrict__ Out,
           const float* __restrict__ R, float scale,
           int K, int lda, int ldb, int ldo,
           size_t sA, size_t sB, size_t sO) {
    A   += (size_t)blockIdx.z * sA;
    B   += (size_t)blockIdx.z * sB;
    Out += (size_t)blockIdx.z * sO;
    if (RESID) R += (size_t)blockIdx.z * sO;

    const int m0 = blockIdx.y * BM;
    const int n0 = blockIdx.x * BN;
    const int tid = threadIdx.x;

    __shared__ float As[BK][SPITCH];
    __shared__ float Bs[BK][SPITCH];

    float acc[8][8];
    #pragma unroll
    for (int i = 0; i < 8; i++)
        #pragma unroll
        for (int j = 0; j < 8; j++) acc[i][j] = 0.f;

    // load-index precompute
    const int ar = tid >> 1, aq = tid & 1;     // AL==0: row, k-quad
    const int ak = tid >> 5, am = tid & 31;    // AL==1: k, m-quad
    const int bk = tid >> 5, bn = tid & 31;    // BL==0: k, n-quad
    const int br = tid >> 1, bq = tid & 1;     // BL==1: row(n), k-quad

    float4 pa, pb;

    // ---- prologue: tile 0 ----
    {
        if (AL == 0) pa = *(const float4*)&A[(size_t)(m0 + ar)*lda + aq*4];
        else         pa = *(const float4*)&A[(size_t)ak*lda + m0 + am*4];
        if (BL == 0) pb = *(const float4*)&B[(size_t)bk*ldb + n0 + bn*4];
        else         pb = *(const float4*)&B[(size_t)(n0 + br)*ldb + bq*4];

        if (AL == 0) {
            As[aq*4+0][ar] = pa.x; As[aq*4+1][ar] = pa.y;
            As[aq*4+2][ar] = pa.z; As[aq*4+3][ar] = pa.w;
        } else *(float4*)&As[ak][am*4] = pa;
        if (BL == 0) *(float4*)&Bs[bk][bn*4] = pb;
        else {
            Bs[bq*4+0][br] = pb.x; Bs[bq*4+1][br] = pb.y;
            Bs[bq*4+2][br] = pb.z; Bs[bq*4+3][br] = pb.w;
        }
    }
    __syncthreads();

    const int ty = tid >> 4, tx = tid & 15;
    const int nk = K / BK;

    for (int kt = 0; kt < nk; kt++) {
        // prefetch next tile into registers
        if (kt + 1 < nk) {
            int k0 = (kt + 1) * BK;
            if (AL == 0) pa = *(const float4*)&A[(size_t)(m0 + ar)*lda + k0 + aq*4];
            else         pa = *(const float4*)&A[(size_t)(k0 + ak)*lda + m0 + am*4];
            if (BL == 0) pb = *(const float4*)&B[(size_t)(k0 + bk)*ldb + n0 + bn*4];
            else         pb = *(const float4*)&B[(size_t)(n0 + br)*ldb + k0 + bq*4];
        }
        // compute current tile
        #pragma unroll
        for (int kk = 0; kk < BK; kk++) {
            float af[8], bf[8];
            *(float4*)&af[0] = *(const float4*)&As[kk][ty*8];
            *(float4*)&af[4] = *(const float4*)&As[kk][ty*8+4];
            *(float4*)&bf[0] = *(const float4*)&Bs[kk][tx*8];
            *(float4*)&bf[4] = *(const float4*)&Bs[kk][tx*8+4];
            #pragma unroll
            for (int i = 0; i < 8; i++)
                #pragma unroll
                for (int j = 0; j < 8; j++)
                    acc[i][j] += af[i]*bf[j];
        }
        __syncthreads();
        if (kt + 1 < nk) {
            if (AL == 0) {
                As[aq*4+0][ar] = pa.x; As[aq*4+1][ar] = pa.y;
                As[aq*4+2][ar] = pa.z; As[aq*4+3][ar] = pa.w;
            } else *(float4*)&As[ak][am*4] = pa;
            if (BL == 0) *(float4*)&Bs[bk][bn*4] = pb;
            else {
                Bs[bq*4+0][br] = pb.x; Bs[bq*4+1][br] = pb.y;
                Bs[bq*4+2][br] = pb.z; Bs[bq*4+3][br] = pb.w;
            }
            __syncthreads();
        }
    }

    // ---- epilogue ----
    #pragma unroll
    for (int i = 0; i < 8; i++) {
        int m = m0 + ty*8 + i;
        float bv = BIAS ? bias[m] : 0.f;
        size_t row = (size_t)m * ldo + n0 + tx*8;
        #pragma unroll
        for (int jq = 0; jq < 2; jq++) {
            float4 o;
            o.x = (acc[i][jq*4+0] + bv) * scale;
            o.y = (acc[i][jq*4+1] + bv) * scale;
            o.z = (acc[i][jq*4+2] + bv) * scale;
            o.w = (acc[i][jq*4+3] + bv) * scale;
            if (RESID) {
                float4 r = *(const float4*)&R[row + jq*4];
                o.x += r.x; o.y += r.y; o.z += r.z; o.w += r.w;
            }
            *(float4*)&Out[row + jq*4] = o;
        }
    }
}

// ---------------- softmax over last dim (row length 4096), in-place on g_s ----
__global__ void softmax_kernel() {
    const size_t row = (size_t)blockIdx.x;     // 0 .. BATCH*NPIX-1
    float* p = g_s + row * NPIX;
    const int tid = threadIdx.x;               // 256

    float v[16];
    float mx = -INFINITY;
    #pragma unroll
    for (int s = 0; s < 4; s++) {
        float4 t = *(const float4*)&p[(tid + 256*s)*4 - tid*4 + tid*4]; // placeholder (see below)
        (void)t;
    }
    // straightforward strided load (coalesced)
    mx = -INFINITY;
    #pragma unroll
    for (int s = 0; s < 16; s++) {
        v[s] = p[tid + 256*s];
        mx = fmaxf(mx, v[s]);
    }
    __shared__ float sh[256];
    sh[tid] = mx; __syncthreads();
    for (int o = 128; o > 0; o >>= 1) {
        if (tid < o) sh[tid] = fmaxf(sh[tid], sh[tid+o]);
        __syncthreads();
    }
    mx = sh[0];
    __syncthreads();

    float sum = 0.f;
    #pragma unroll
    for (int s = 0; s < 16; s++) {
        v[s] = __expf(v[s] - mx);
        sum += v[s];
    }
    sh[tid] = sum; __syncthreads();
    for (int o = 128; o > 0; o >>= 1) {
        if (tid < o) sh[tid] += sh[tid+o];
        __syncthreads();
    }
    float inv = 1.0f / sh[0];
    #pragma unroll
    for (int s = 0; s < 16; s++)
        p[tid + 256*s] = v[s] * inv;
}

// ---------------- launch ----------------
extern "C" void kernel_launch(void* const* d_in, const int* in_sizes, int n_in,
                              void* d_out, int out_size) {
    const float* x     = (const float*)d_in[0];
    const float* gamma = (const float*)d_in[1];
    const float* beta  = (const float*)d_in[2];
    const float* wq = (const float*)d_in[3];
    const float* bq = (const float*)d_in[4];
    const float* wk = (const float*)d_in[5];
    const float* bk = (const float*)d_in[6];
    const float* wv = (const float*)d_in[7];
    const float* bv = (const float*)d_in[8];
    const float* wp = (const float*)d_in[9];
    const float* bp = (const float*)d_in[10];
    float* out = (float*)d_out;

    float *p_h, *p_q, *p_k, *p_v, *p_o, *p_s;
    cudaGetSymbolAddress((void**)&p_h, g_h);
    cudaGetSymbolAddress((void**)&p_q, g_q);
    cudaGetSymbolAddress((void**)&p_k, g_k);
    cudaGetSymbolAddress((void**)&p_v, g_v);
    cudaGetSymbolAddress((void**)&p_o, g_o);
    cudaGetSymbolAddress((void**)&p_s, g_s);

    const size_t sCN = (size_t)CH * NPIX;
    const size_t sNN = (size_t)NPIX * NPIX;

    // 1. GroupNorm
    groupnorm_kernel<<<BATCH*NGRP, 256>>>(x, gamma, beta);

    // 2. q/k/v 1x1 convs: A=W (K-major), B=h (N-major), bias, no resid
    dim3 gq(NPIX/BN, CH/BM, BATCH);
    sgemm<0,0,true,false><<<gq, 256>>>(wq, p_h, bq, p_q, nullptr, 1.0f,
                                       CH, CH, NPIX, NPIX, 0, sCN, sCN);
    sgemm<0,0,true,false><<<gq, 256>>>(wk, p_h, bk, p_k, nullptr, 1.0f,
                                       CH, CH, NPIX, NPIX, 0, sCN, sCN);
    sgemm<0,0,true,false><<<gq, 256>>>(wv, p_h, bv, p_v, nullptr, 1.0f,
                                       CH, CH, NPIX, NPIX, 0, sCN, sCN);

    // 3. scores = (q^T k) * C^-0.5 : A=q (M contiguous), B=k (N contiguous)
    dim3 gs(NPIX/BN, NPIX/BM, BATCH);
    sgemm<1,0,false,false><<<gs, 256>>>(p_q, p_k, nullptr, p_s, nullptr, QSCALE,
                                        CH, NPIX, NPIX, NPIX, sCN, sCN, sNN);

    // 4. softmax over keys
    softmax_kernel<<<BATCH*NPIX, 256>>>();

    // 5. o[c,i] = sum_j v[c,j] * attn[i,j] : A=v (K-major), B=attn (K-major)
    sgemm<0,1,false,false><<<gq, 256>>>(p_v, p_s, nullptr, p_o, nullptr, 1.0f,
                                        NPIX, NPIX, NPIX, NPIX, sCN, sNN, sCN);

    // 6. proj + bias + residual
    sgemm<0,0,true,true><<<gq, 256>>>(wp, p_o, bp, out, x, 1.0f,
                                      CH, CH, NPIX, NPIX, 0, sCN, sCN);
}

// round 5
// speedup vs baseline: 2.8241x; 1.7393x over previous
#include <cuda_runtime.h>
#include <cuda_bf16.h>
#include <cstdint>
#include <math.h>

#define BATCH 2
#define CH    256
#define NPIX  4096
#define NGRP  32
#define CPG   (CH/NGRP)
#define GN_EPS 1e-6f
#define QSCALE 0.0625f

// ---------------- scratch (static device globals; no allocation) ----------------
__device__ __align__(256) float g_s[(size_t)BATCH*NPIX*NPIX];                 // scores fp32
__device__ __align__(256) __nv_bfloat16 g_hh[BATCH*CH*NPIX], g_hl[BATCH*CH*NPIX];
__device__ __align__(256) __nv_bfloat16 g_qh[BATCH*CH*NPIX], g_ql[BATCH*CH*NPIX];
__device__ __align__(256) __nv_bfloat16 g_kh[BATCH*CH*NPIX], g_kl[BATCH*CH*NPIX];
__device__ __align__(256) __nv_bfloat16 g_vh[BATCH*CH*NPIX], g_vl[BATCH*CH*NPIX];
__device__ __align__(256) __nv_bfloat16 g_oh[BATCH*CH*NPIX], g_ol[BATCH*CH*NPIX];
__device__ __align__(256) __nv_bfloat16 g_ah[(size_t)BATCH*NPIX*NPIX];
__device__ __align__(256) __nv_bfloat16 g_al[(size_t)BATCH*NPIX*NPIX];
__device__ __align__(256) __nv_bfloat16 g_wh[4*CH*CH], g_wl[4*CH*CH];         // wq,wk,wv,wp split

// ---------------- PTX helpers (baseline sm_80+ features only) ----------------
__device__ __forceinline__ uint32_t cvta_smem(const void* p) {
    uint32_t a;
    asm("{ .reg .u64 t; cvta.to.shared.u64 t, %1; cvt.u32.u64 %0, t; }" : "=r"(a) : "l"(p));
    return a;
}
__device__ __forceinline__ void cp16(uint32_t s, const void* g) {
    asm volatile("cp.async.cg.shared.global [%0], [%1], 16;" :: "r"(s), "l"(g) : "memory");
}
__device__ __forceinline__ void cp_commit() { asm volatile("cp.async.commit_group;" ::: "memory"); }
template<int N> __device__ __forceinline__ void cp_wait() {
    asm volatile("cp.async.wait_group %0;" :: "n"(N) : "memory");
}
__device__ __forceinline__ void ldsm4(uint32_t& r0, uint32_t& r1, uint32_t& r2, uint32_t& r3, uint32_t a) {
    asm volatile("ldmatrix.sync.aligned.m8n8.x4.shared.b16 {%0,%1,%2,%3}, [%4];"
                 : "=r"(r0), "=r"(r1), "=r"(r2), "=r"(r3) : "r"(a));
}
__device__ __forceinline__ void ldsm4t(uint32_t& r0, uint32_t& r1, uint32_t& r2, uint32_t& r3, uint32_t a) {
    asm volatile("ldmatrix.sync.aligned.m8n8.x4.trans.shared.b16 {%0,%1,%2,%3}, [%4];"
                 : "=r"(r0), "=r"(r1), "=r"(r2), "=r"(r3) : "r"(a));
}
__device__ __forceinline__ void ldsm2(uint32_t& r0, uint32_t& r1, uint32_t a) {
    asm volatile("ldmatrix.sync.aligned.m8n8.x2.shared.b16 {%0,%1}, [%2];"
                 : "=r"(r0), "=r"(r1) : "r"(a));
}
__device__ __forceinline__ void ldsm2t(uint32_t& r0, uint32_t& r1, uint32_t a) {
    asm volatile("ldmatrix.sync.aligned.m8n8.x2.trans.shared.b16 {%0,%1}, [%2];"
                 : "=r"(r0), "=r"(r1) : "r"(a));
}
#define MMA_OP(d, a0,a1,a2,a3, b0,b1) \
    asm volatile("mma.sync.aligned.m16n8k16.row.col.f32.bf16.bf16.f32 " \
                 "{%0,%1,%2,%3}, {%4,%5,%6,%7}, {%8,%9}, {%0,%1,%2,%3};" \
                 : "+f"((d)[0]), "+f"((d)[1]), "+f"((d)[2]), "+f"((d)[3]) \
                 : "r"(a0), "r"(a1), "r"(a2), "r"(a3), "r"(b0), "r"(b1))

__device__ __forceinline__ void split2(float v0, float v1,
                                       __nv_bfloat162& h2, __nv_bfloat162& l2) {
    h2.x = __float2bfloat16(v0);           h2.y = __float2bfloat16(v1);
    l2.x = __float2bfloat16(v0 - __bfloat162float(h2.x));
    l2.y = __float2bfloat16(v1 - __bfloat162float(h2.y));
}

// ================= split-bf16 mma.sync GEMM =================
// D[m][n] = scale*( sum_k (Ah+Al)[m,k]*(Bh+Bl)[n,k] + bias[m] ) (+R), 3-term split.
// ALAY: 0 = A[m*lda+k] (k contig), 1 = A[k*lda+m] (m contig, trans-ldmatrix)
// BLAY: 0 = B[n*ldb+k] (k contig), 1 = B[k*ldb+n] (n contig, trans-ldmatrix)
// EPI : 0 = fp32 OutF,  1 = bf16 split Oh/Ol (natural [m][n] layout)
// Tile 128x128, BK=32, 8 warps (64x32 each), 4-stage cp.async pipeline.
template<int ALAY, int BLAY, int EPI, bool BIAS, bool RESID>
__global__ __launch_bounds__(256)
void mma_gemm(const __nv_bfloat16* __restrict__ Ah, const __nv_bfloat16* __restrict__ Al,
              const __nv_bfloat16* __restrict__ Bh, const __nv_bfloat16* __restrict__ Bl,
              const float* __restrict__ bias, float* __restrict__ OutF,
              __nv_bfloat16* __restrict__ Oh, __nv_bfloat16* __restrict__ Ol,
              const float* __restrict__ R, float scale,
              int K, int lda, int ldb, int ldo,
              size_t sA, size_t sB, size_t sO)
{
    constexpr uint32_t ASZ = (ALAY == 0) ? 128u*80u : 32u*272u;
    constexpr uint32_t BSZ = (BLAY == 0) ? 128u*80u : 32u*272u;
    constexpr int STAGES = 4;

    extern __shared__ char smem[];
    const uint32_t sbase = cvta_smem(smem);

    Ah += (size_t)blockIdx.z * sA;  Al += (size_t)blockIdx.z * sA;
    Bh += (size_t)blockIdx.z * sB;  Bl += (size_t)blockIdx.z * sB;
    if (EPI == 0) OutF += (size_t)blockIdx.z * sO;
    else { Oh += (size_t)blockIdx.z * sO; Ol += (size_t)blockIdx.z * sO; }
    if (RESID) R += (size_t)blockIdx.z * sO;

    const int tid  = threadIdx.x;
    const int lane = tid & 31;
    const int wid  = tid >> 5;
    const int wm   = wid >> 2;      // 0..1
    const int wn   = wid & 3;       // 0..3
    const int m0   = blockIdx.y * 128;
    const int n0   = blockIdx.x * 128;

    float acc[4][4][4];
    #pragma unroll
    for (int a = 0; a < 4; a++)
        #pragma unroll
        for (int b = 0; b < 4; b++)
            #pragma unroll
            for (int c = 0; c < 4; c++) acc[a][b][c] = 0.f;

    const int kseg = K / 32;
    const int S = 3 * kseg;

    auto load_stage = [&](int s, int slot) {
        const int seg = s / kseg;
        const int k0  = (s - seg * kseg) * 32;
        const __nv_bfloat16* Asrc = (seg == 2) ? Al : Ah;
        const __nv_bfloat16* Bsrc = (seg == 1) ? Bl : Bh;
        const uint32_t ab = sbase + (uint32_t)slot * (ASZ + BSZ);
        const uint32_t bb = ab + ASZ;
        #pragma unroll
        for (int r = 0; r < 2; r++) {
            const int id = tid + 256 * r;
            if (ALAY == 0) {
                int row = id >> 2, c = id & 3;
                cp16(ab + (uint32_t)row*80u + (uint32_t)c*16u,
                     Asrc + (size_t)(m0 + row)*lda + k0 + c*8);
            } else {
                int row = id >> 4, c = id & 15;
                cp16(ab + (uint32_t)row*272u + (uint32_t)c*16u,
                     Asrc + (size_t)(k0 + row)*lda + m0 + c*8);
            }
            if (BLAY == 0) {
                int row = id >> 2, c = id & 3;
                cp16(bb + (uint32_t)row*80u + (uint32_t)c*16u,
                     Bsrc + (size_t)(n0 + row)*ldb + k0 + c*8);
            } else {
                int row = id >> 4, c = id & 15;
                cp16(bb + (uint32_t)row*272u + (uint32_t)c*16u,
                     Bsrc + (size_t)(k0 + row)*ldb + n0 + c*8);
            }
        }
        cp_commit();
    };

    // lane components for ldmatrix addressing
    const int g4   = lane >> 3;
    const int lr8  = lane & 7;
    const int at_k = lr8 + (g4 & 1) * 8;        // A-trans: k within 16
    const int at_m = (g4 >> 1) * 8;             // A-trans: m half
    const int ap_r = lane & 15;                 // A-plain: m row
    const int ap_c = lane >> 4;                 // A-plain: k half (16B)
    const int bp_r = lane & 7;                  // B-plain: n row
    const int bp_g = (lane >> 3) & 1;           // B-plain: k half
    const int bt_k = ((lane >> 3) & 1) * 8 + (lane & 7);  // B-trans: k row

    const int pre = (S < STAGES - 1) ? S : (STAGES - 1);
    for (int p = 0; p < pre; p++) load_stage(p, p);

    for (int s = 0; s < S; s++) {
        cp_wait<STAGES - 2>();
        __syncthreads();
        if (s + STAGES - 1 < S) load_stage(s + STAGES - 1, (s + STAGES - 1) % STAGES);

        const uint32_t ab = sbase + (uint32_t)(s % STAGES) * (ASZ + BSZ);
        const uint32_t bb = ab + ASZ;

        #pragma unroll
        for (int kk = 0; kk < 2; kk++) {
            uint32_t A0[4], A1[4], A2[4], A3[4];
            #pragma unroll
            for (int mi = 0; mi < 4; mi++) {
                uint32_t r0, r1, r2, r3, addr;
                if (ALAY == 0) {
                    addr = ab + (uint32_t)(wm*64 + mi*16 + ap_r)*80u
                              + (uint32_t)(kk*32 + ap_c*16);
                    ldsm4(r0, r1, r2, r3, addr);
                    A0[mi] = r0; A1[mi] = r1; A2[mi] = r2; A3[mi] = r3;
                } else {
                    addr = ab + (uint32_t)(kk*16 + at_k)*272u
                              + (uint32_t)(wm*64 + mi*16 + at_m)*2u;
                    ldsm4t(r0, r1, r2, r3, addr);
                    A0[mi] = r0; A1[mi] = r2; A2[mi] = r1; A3[mi] = r3;   // reorder
                }
            }
            uint32_t B0[4], B1[4];
            #pragma unroll
            for (int ni = 0; ni < 4; ni++) {
                uint32_t r0, r1, addr;
                if (BLAY == 0) {
                    addr = bb + (uint32_t)(wn*32 + ni*8 + bp_r)*80u
                              + (uint32_t)(kk*32 + bp_g*16);
                    ldsm2(r0, r1, addr);
                } else {
                    addr = bb + (uint32_t)(kk*16 + bt_k)*272u
                              + (uint32_t)(wn*32 + ni*8)*2u;
                    ldsm2t(r0, r1, addr);
                }
                B0[ni] = r0; B1[ni] = r1;
            }
            #pragma unroll
            for (int mi = 0; mi < 4; mi++)
                #pragma unroll
                for (int ni = 0; ni < 4; ni++)
                    MMA_OP(acc[mi][ni], A0[mi], A1[mi], A2[mi], A3[mi], B0[ni], B1[ni]);
        }
    }

    // ---------------- epilogue ----------------
    const int em = (lane >> 2);
    const int en = (lane & 3) * 2;
    #pragma unroll
    for (int mi = 0; mi < 4; mi++) {
        const int mA = m0 + wm*64 + mi*16 + em;
        const int mB = mA + 8;
        const float bvA = BIAS ? bias[mA] : 0.f;
        const float bvB = BIAS ? bias[mB] : 0.f;
        #pragma unroll
        for (int ni = 0; ni < 4; ni++) {
            const int n = n0 + wn*32 + ni*8 + en;
            float* d = acc[mi][ni];
            if (EPI == 0) {
                float2 oA = { (d[0] + bvA)*scale, (d[1] + bvA)*scale };
                float2 oB = { (d[2] + bvB)*scale, (d[3] + bvB)*scale };
                if (RESID) {
                    float2 rA = *(const float2*)&R[(size_t)mA*ldo + n];
                    float2 rB = *(const float2*)&R[(size_t)mB*ldo + n];
                    oA.x += rA.x; oA.y += rA.y; oB.x += rB.x; oB.y += rB.y;
                }
                *(float2*)&OutF[(size_t)mA*ldo + n] = oA;
                *(float2*)&OutF[(size_t)mB*ldo + n] = oB;
            } else {
                __nv_bfloat162 h2, l2;
                split2(d[0] + bvA, d[1] + bvA, h2, l2);
                *(__nv_bfloat162*)&Oh[(size_t)mA*ldo + n] = h2;
                *(__nv_bfloat162*)&Ol[(size_t)mA*ldo + n] = l2;
                split2(d[2] + bvB, d[3] + bvB, h2, l2);
                *(__nv_bfloat162*)&Oh[(size_t)mB*ldo + n] = h2;
                *(__nv_bfloat162*)&Ol[(size_t)mB*ldo + n] = l2;
            }
        }
    }
}

// ---------------- weight split: fp32 -> bf16 hi/lo, all 4 matrices ----------------
__global__ void wsplit4(const float* __restrict__ w0, const float* __restrict__ w1,
                        const float* __restrict__ w2, const float* __restrict__ w3) {
    const int i = blockIdx.x * 256 + threadIdx.x;   // 0..65535
    const float* ws[4] = { w0, w1, w2, w3 };
    #pragma unroll
    for (int j = 0; j < 4; j++) {
        float v = ws[j][i];
        __nv_bfloat16 h = __float2bfloat16(v);
        g_wh[j*CH*CH + i] = h;
        g_wl[j*CH*CH + i] = __float2bfloat16(v - __bfloat162float(h));
    }
}

// ---------------- GroupNorm -> bf16 split h ----------------
__global__ void groupnorm_kernel(const float* __restrict__ x,
                                 const float* __restrict__ gamma,
                                 const float* __restrict__ beta) {
    int bg = blockIdx.x;
    int b  = bg / NGRP;
    int g  = bg % NGRP;
    const size_t base = ((size_t)b*CH + (size_t)g*CPG) * NPIX;
    const float4* xp4 = (const float4*)(x + base);
    const int tid = threadIdx.x;
    const int NV = CPG*NPIX/4;

    float s = 0.f, s2 = 0.f;
    for (int i = tid; i < NV; i += 256) {
        float4 v = xp4[i];
        s  += v.x + v.y + v.z + v.w;
        s2 += v.x*v.x + v.y*v.y + v.z*v.z + v.w*v.w;
    }
    __shared__ float sh[256], sh2[256];
    sh[tid] = s; sh2[tid] = s2;
    __syncthreads();
    for (int o = 128; o > 0; o >>= 1) {
        if (tid < o) { sh[tid] += sh[tid+o]; sh2[tid] += sh2[tid+o]; }
        __syncthreads();
    }
    float inv_n = 1.0f / (float)(CPG*NPIX);
    float mean  = sh[0] * inv_n;
    float var   = sh2[0] * inv_n - mean*mean;
    float rstd  = rsqrtf(var + GN_EPS);

    __nv_bfloat162* hh2 = (__nv_bfloat162*)(g_hh + base);
    __nv_bfloat162* hl2 = (__nv_bfloat162*)(g_hl + base);
    for (int i = tid; i < NV; i += 256) {
        int ch = g*CPG + (i*4) / NPIX;
        float ga = gamma[ch] * rstd;
        float be = beta[ch] - mean * ga;
        float4 v = xp4[i];
        __nv_bfloat162 h2, l2;
        split2(v.x*ga + be, v.y*ga + be, h2, l2);
        hh2[i*2]   = h2; hl2[i*2]   = l2;
        split2(v.z*ga + be, v.w*ga + be, h2, l2);
        hh2[i*2+1] = h2; hl2[i*2+1] = l2;
    }
}

// ---------------- softmax: fp32 scores -> bf16 split attn ----------------
__global__ void softmax_kernel() {
    const size_t row = (size_t)blockIdx.x;
    float* p = g_s + row * NPIX;
    __nv_bfloat16* ph = g_ah + row * NPIX;
    __nv_bfloat16* pl = g_al + row * NPIX;
    const int tid = threadIdx.x;

    float v[16];
    float mx = -INFINITY;
    #pragma unroll
    for (int s = 0; s < 16; s++) {
        v[s] = p[tid + 256*s];
        mx = fmaxf(mx, v[s]);
    }
    __shared__ float sh[256];
    sh[tid] = mx; __syncthreads();
    for (int o = 128; o > 0; o >>= 1) {
        if (tid < o) sh[tid] = fmaxf(sh[tid], sh[tid+o]);
        __syncthreads();
    }
    mx = sh[0];
    __syncthreads();

    float sum = 0.f;
    #pragma unroll
    for (int s = 0; s < 16; s++) {
        v[s] = __expf(v[s] - mx);
        sum += v[s];
    }
    sh[tid] = sum; __syncthreads();
    for (int o = 128; o > 0; o >>= 1) {
        if (tid < o) sh[tid] += sh[tid+o];
        __syncthreads();
    }
    float inv = 1.0f / sh[0];
    #pragma unroll
    for (int s = 0; s < 16; s++) {
        float w = v[s] * inv;
        __nv_bfloat16 h = __float2bfloat16(w);
        ph[tid + 256*s] = h;
        pl[tid + 256*s] = __float2bfloat16(w - __bfloat162float(h));
    }
}

// ---------------- launch ----------------
extern "C" void kernel_launch(void* const* d_in, const int* in_sizes, int n_in,
                              void* d_out, int out_size) {
    const float* x     = (const float*)d_in[0];
    const float* gamma = (const float*)d_in[1];
    const float* beta  = (const float*)d_in[2];
    const float* wq = (const float*)d_in[3];
    const float* bq = (const float*)d_in[4];
    const float* wk = (const float*)d_in[5];
    const float* bk = (const float*)d_in[6];
    const float* wv = (const float*)d_in[7];
    const float* bv = (const float*)d_in[8];
    const float* wp = (const float*)d_in[9];
    const float* bp = (const float*)d_in[10];
    float* out = (float*)d_out;

    float* p_s;
    __nv_bfloat16 *p_hh, *p_hl, *p_qh, *p_ql, *p_kh, *p_kl, *p_vh, *p_vl;
    __nv_bfloat16 *p_oh, *p_ol, *p_ah, *p_al, *p_wh, *p_wl;
    cudaGetSymbolAddress((void**)&p_s,  g_s);
    cudaGetSymbolAddress((void**)&p_hh, g_hh); cudaGetSymbolAddress((void**)&p_hl, g_hl);
    cudaGetSymbolAddress((void**)&p_qh, g_qh); cudaGetSymbolAddress((void**)&p_ql, g_ql);
    cudaGetSymbolAddress((void**)&p_kh, g_kh); cudaGetSymbolAddress((void**)&p_kl, g_kl);
    cudaGetSymbolAddress((void**)&p_vh, g_vh); cudaGetSymbolAddress((void**)&p_vl, g_vl);
    cudaGetSymbolAddress((void**)&p_oh, g_oh); cudaGetSymbolAddress((void**)&p_ol, g_ol);
    cudaGetSymbolAddress((void**)&p_ah, g_ah); cudaGetSymbolAddress((void**)&p_al, g_al);
    cudaGetSymbolAddress((void**)&p_wh, g_wh); cudaGetSymbolAddress((void**)&p_wl, g_wl);

    // smem sizes: plain=128*80, trans=32*272, 4 stages
    const int SM_QKV = 4 * (128*80 + 32*272);   // 75776  (A plain, B trans)
    const int SM_SCO = 4 * (32*272 + 32*272);   // 69632  (both trans)
    const int SM_PV  = 4 * (128*80 + 128*80);   // 81920  (both plain)
    const int SM_PRJ = SM_QKV;
    cudaFuncSetAttribute(mma_gemm<0,1,1,true,false>,  cudaFuncAttributeMaxDynamicSharedMemorySize, SM_QKV);
    cudaFuncSetAttribute(mma_gemm<1,1,0,false,false>, cudaFuncAttributeMaxDynamicSharedMemorySize, SM_SCO);
    cudaFuncSetAttribute(mma_gemm<0,0,1,false,false>, cudaFuncAttributeMaxDynamicSharedMemorySize, SM_PV);
    cudaFuncSetAttribute(mma_gemm<0,1,0,true,true>,   cudaFuncAttributeMaxDynamicSharedMemorySize, SM_PRJ);

    const size_t sCN = (size_t)CH * NPIX;
    const size_t sNN = (size_t)NPIX * NPIX;

    // 0. split weights to bf16 hi/lo
    wsplit4<<<CH*CH/256, 256>>>(wq, wk, wv, wp);

    // 1. GroupNorm -> h split
    groupnorm_kernel<<<BATCH*NGRP, 256>>>(x, gamma, beta);

    // 2. q/k/v: A = W [oc][ic] plain; B = h [c][n] trans; out bf16 split (c,n)
    dim3 gq(NPIX/128, CH/128, BATCH);
    mma_gemm<0,1,1,true,false><<<gq, 256, SM_QKV>>>(
        p_wh + 0*CH*CH, p_wl + 0*CH*CH, p_hh, p_hl, bq, nullptr, p_qh, p_ql,
        nullptr, 1.0f, CH, CH, NPIX, NPIX, 0, sCN, sCN);
    mma_gemm<0,1,1,true,false><<<gq, 256, SM_QKV>>>(
        p_wh + 1*CH*CH, p_wl + 1*CH*CH, p_hh, p_hl, bk, nullptr, p_kh, p_kl,
        nullptr, 1.0f, CH, CH, NPIX, NPIX, 0, sCN, sCN);
    mma_gemm<0,1,1,true,false><<<gq, 256, SM_QKV>>>(
        p_wh + 2*CH*CH, p_wl + 2*CH*CH, p_hh, p_hl, bv, nullptr, p_vh, p_vl,
        nullptr, 1.0f, CH, CH, NPIX, NPIX, 0, sCN, sCN);

    // 3. scores[i][j] = q[c][i].k[c][j] * C^-0.5 : both operands [c][*] trans
    dim3 gsc(NPIX/128, NPIX/128, BATCH);
    mma_gemm<1,1,0,false,false><<<gsc, 256, SM_SCO>>>(
        p_qh, p_ql, p_kh, p_kl, nullptr, p_s, nullptr, nullptr,
        nullptr, QSCALE, CH, NPIX, NPIX, NPIX, sCN, sCN, sNN);

    // 4. softmax -> attn split
    softmax_kernel<<<BATCH*NPIX, 256>>>();

    // 5. o[c][i] = sum_j v[c][j]*attn[i][j] : A = v plain, B = attn plain; out split (c,n)
    dim3 gpv(NPIX/128, CH/128, BATCH);
    mma_gemm<0,0,1,false,false><<<gpv, 256, SM_PV>>>(
        p_vh, p_vl, p_ah, p_al, nullptr, nullptr, p_oh, p_ol,
        nullptr, 1.0f, NPIX, NPIX, NPIX, NPIX, sCN, sNN, sCN);

    // 6. proj: A = Wp plain, B = o [c][n] trans; fp32 out + bias + residual
    mma_gemm<0,1,0,true,true><<<gpv, 256, SM_QKV>>>(
        p_wh + 3*CH*CH, p_wl + 3*CH*CH, p_oh, p_ol, bp, out, nullptr, nullptr,
        x, 1.0f, CH, CH, NPIX, NPIX, 0, sCN, sCN);
}

// round 6
// speedup vs baseline: 7.7754x; 2.7532x over previous
#include <cuda_runtime.h>
#include <cuda_bf16.h>
#include <cstdint>
#include <math.h>

#define BATCH 2
#define CH    256
#define NPIX  4096
#define NGRP  32
#define CPG   (CH/NGRP)
#define GN_EPS 1e-6f
#define QSCALE 0.0625f

// ---------------- scratch (static device globals; no allocation) ----------------
__device__ __align__(256) __nv_bfloat16 g_sb[(size_t)BATCH*NPIX*NPIX]; // scores/attn bf16 (in-place softmax)
__device__ __align__(256) __nv_bfloat16 g_hb[BATCH*CH*NPIX];
__device__ __align__(256) __nv_bfloat16 g_qb[BATCH*CH*NPIX];
__device__ __align__(256) __nv_bfloat16 g_kb[BATCH*CH*NPIX];
__device__ __align__(256) __nv_bfloat16 g_vb[BATCH*CH*NPIX];
__device__ __align__(256) __nv_bfloat16 g_ob[BATCH*CH*NPIX];
__device__ __align__(256) __nv_bfloat16 g_wb[3*CH*CH];   // stacked wq,wk,wv bf16
__device__ __align__(256) __nv_bfloat16 g_wpb[CH*CH];
__device__ __align__(256) float         g_bias[3*CH];    // stacked bq,bk,bv

// ---------------- PTX helpers (baseline sm_80+ features only) ----------------
__device__ __forceinline__ uint32_t cvta_smem(const void* p) {
    uint32_t a;
    asm("{ .reg .u64 t; cvta.to.shared.u64 t, %1; cvt.u32.u64 %0, t; }" : "=r"(a) : "l"(p));
    return a;
}
__device__ __forceinline__ void cp16(uint32_t s, const void* g) {
    asm volatile("cp.async.cg.shared.global [%0], [%1], 16;" :: "r"(s), "l"(g) : "memory");
}
__device__ __forceinline__ void cp_commit() { asm volatile("cp.async.commit_group;" ::: "memory"); }
template<int N> __device__ __forceinline__ void cp_wait() {
    asm volatile("cp.async.wait_group %0;" :: "n"(N) : "memory");
}
__device__ __forceinline__ void ldsm4(uint32_t& r0, uint32_t& r1, uint32_t& r2, uint32_t& r3, uint32_t a) {
    asm volatile("ldmatrix.sync.aligned.m8n8.x4.shared.b16 {%0,%1,%2,%3}, [%4];"
                 : "=r"(r0), "=r"(r1), "=r"(r2), "=r"(r3) : "r"(a));
}
__device__ __forceinline__ void ldsm4t(uint32_t& r0, uint32_t& r1, uint32_t& r2, uint32_t& r3, uint32_t a) {
    asm volatile("ldmatrix.sync.aligned.m8n8.x4.trans.shared.b16 {%0,%1,%2,%3}, [%4];"
                 : "=r"(r0), "=r"(r1), "=r"(r2), "=r"(r3) : "r"(a));
}
__device__ __forceinline__ void ldsm2(uint32_t& r0, uint32_t& r1, uint32_t a) {
    asm volatile("ldmatrix.sync.aligned.m8n8.x2.shared.b16 {%0,%1}, [%2];"
                 : "=r"(r0), "=r"(r1) : "r"(a));
}
__device__ __forceinline__ void ldsm2t(uint32_t& r0, uint32_t& r1, uint32_t a) {
    asm volatile("ldmatrix.sync.aligned.m8n8.x2.trans.shared.b16 {%0,%1}, [%2];"
                 : "=r"(r0), "=r"(r1) : "r"(a));
}
#define MMA_OP(d, a0,a1,a2,a3, b0,b1) \
    asm volatile("mma.sync.aligned.m16n8k16.row.col.f32.bf16.bf16.f32 " \
                 "{%0,%1,%2,%3}, {%4,%5,%6,%7}, {%8,%9}, {%0,%1,%2,%3};" \
                 : "+f"((d)[0]), "+f"((d)[1]), "+f"((d)[2]), "+f"((d)[3]) \
                 : "r"(a0), "r"(a1), "r"(a2), "r"(a3), "r"(b0), "r"(b1))

__device__ __forceinline__ __nv_bfloat162 pack_bf2(float v0, float v1) {
    __nv_bfloat162 r;
    r.x = __float2bfloat16(v0);
    r.y = __float2bfloat16(v1);
    return r;
}

// ================= bf16 mma.sync GEMM (single-term, fp32 accum) =================
// ALAY: 0 = A[m*lda+k] (k contig), 1 = A[k*lda+m] (m contig, trans-ldmatrix)
// BLAY: 0 = B[n*ldb+k] (k contig), 1 = B[k*ldb+n] (n contig, trans-ldmatrix)
// EPI : 0 = fp32 OutF = (acc + bias[m])*scale + R
//       1 = bf16 O0[m*ldo+n] = acc*scale
//       2 = fused qkv: route by global m segment to O0/O1/O2; +bias[m]; q scaled
// Tile 128x128, BK=32, 8 warps (64x32 each), STAGES-deep cp.async pipeline.
template<int ALAY, int BLAY, int EPI, int STAGES>
__global__ __launch_bounds__(256, 2)
void mma_gemm(const __nv_bfloat16* __restrict__ A, const __nv_bfloat16* __restrict__ B,
              const float* __restrict__ bias, float* __restrict__ OutF,
              __nv_bfloat16* __restrict__ O0, __nv_bfloat16* __restrict__ O1,
              __nv_bfloat16* __restrict__ O2,
              const float* __restrict__ R, float scale,
              int K, int lda, int ldb, int ldo,
              size_t sA, size_t sB, size_t sO)
{
    constexpr uint32_t ASZ = (ALAY == 0) ? 128u*80u : 32u*272u;
    constexpr uint32_t BSZ = (BLAY == 0) ? 128u*80u : 32u*272u;

    extern __shared__ char smem[];
    const uint32_t sbase = cvta_smem(smem);

    A += (size_t)blockIdx.z * sA;
    B += (size_t)blockIdx.z * sB;
    if (EPI == 0) { OutF += (size_t)blockIdx.z * sO; R += (size_t)blockIdx.z * sO; }
    else if (EPI == 1) O0 += (size_t)blockIdx.z * sO;
    else { O0 += (size_t)blockIdx.z * sO; O1 += (size_t)blockIdx.z * sO; O2 += (size_t)blockIdx.z * sO; }

    const int tid  = threadIdx.x;
    const int lane = tid & 31;
    const int wid  = tid >> 5;
    const int wm   = wid >> 2;
    const int wn   = wid & 3;
    const int m0   = blockIdx.y * 128;
    const int n0   = blockIdx.x * 128;

    float acc[4][4][4];
    #pragma unroll
    for (int a = 0; a < 4; a++)
        #pragma unroll
        for (int b = 0; b < 4; b++)
            #pragma unroll
            for (int c = 0; c < 4; c++) acc[a][b][c] = 0.f;

    const int S = K / 32;

    auto load_stage = [&](int s, int slot) {
        const int k0 = s * 32;
        const uint32_t ab = sbase + (uint32_t)slot * (ASZ + BSZ);
        const uint32_t bb = ab + ASZ;
        #pragma unroll
        for (int r = 0; r < 2; r++) {
            const int id = tid + 256 * r;
            if (ALAY == 0) {
                int row = id >> 2, c = id & 3;
                cp16(ab + (uint32_t)row*80u + (uint32_t)c*16u,
                     A + (size_t)(m0 + row)*lda + k0 + c*8);
            } else {
                int row = id >> 4, c = id & 15;
                cp16(ab + (uint32_t)row*272u + (uint32_t)c*16u,
                     A + (size_t)(k0 + row)*lda + m0 + c*8);
            }
            if (BLAY == 0) {
                int row = id >> 2, c = id & 3;
                cp16(bb + (uint32_t)row*80u + (uint32_t)c*16u,
                     B + (size_t)(n0 + row)*ldb + k0 + c*8);
            } else {
                int row = id >> 4, c = id & 15;
                cp16(bb + (uint32_t)row*272u + (uint32_t)c*16u,
                     B + (size_t)(k0 + row)*ldb + n0 + c*8);
            }
        }
        cp_commit();
    };

    const int g4   = lane >> 3;
    const int lr8  = lane & 7;
    const int at_k = lr8 + (g4 & 1) * 8;
    const int at_m = (g4 >> 1) * 8;
    const int ap_r = lane & 15;
    const int ap_c = lane >> 4;
    const int bp_r = lane & 7;
    const int bp_g = (lane >> 3) & 1;
    const int bt_k = ((lane >> 3) & 1) * 8 + (lane & 7);

    const int pre = (S < STAGES - 1) ? S : (STAGES - 1);
    for (int p = 0; p < pre; p++) load_stage(p, p);

    for (int s = 0; s < S; s++) {
        cp_wait<STAGES - 2>();
        __syncthreads();
        if (s + STAGES - 1 < S) load_stage(s + STAGES - 1, (s + STAGES - 1) % STAGES);

        const uint32_t ab = sbase + (uint32_t)(s % STAGES) * (ASZ + BSZ);
        const uint32_t bb = ab + ASZ;

        #pragma unroll
        for (int kk = 0; kk < 2; kk++) {
            uint32_t A0[4], A1[4], A2[4], A3[4];
            #pragma unroll
            for (int mi = 0; mi < 4; mi++) {
                uint32_t r0, r1, r2, r3, addr;
                if (ALAY == 0) {
                    addr = ab + (uint32_t)(wm*64 + mi*16 + ap_r)*80u
                              + (uint32_t)(kk*32 + ap_c*16);
                    ldsm4(r0, r1, r2, r3, addr);
                    A0[mi] = r0; A1[mi] = r1; A2[mi] = r2; A3[mi] = r3;
                } else {
                    addr = ab + (uint32_t)(kk*16 + at_k)*272u
                              + (uint32_t)(wm*64 + mi*16 + at_m)*2u;
                    ldsm4t(r0, r1, r2, r3, addr);
                    A0[mi] = r0; A1[mi] = r2; A2[mi] = r1; A3[mi] = r3;
                }
            }
            uint32_t B0[4], B1[4];
            #pragma unroll
            for (int ni = 0; ni < 4; ni++) {
                uint32_t r0, r1, addr;
                if (BLAY == 0) {
                    addr = bb + (uint32_t)(wn*32 + ni*8 + bp_r)*80u
                              + (uint32_t)(kk*32 + bp_g*16);
                    ldsm2(r0, r1, addr);
                } else {
                    addr = bb + (uint32_t)(kk*16 + bt_k)*272u
                              + (uint32_t)(wn*32 + ni*8)*2u;
                    ldsm2t(r0, r1, addr);
                }
                B0[ni] = r0; B1[ni] = r1;
            }
            #pragma unroll
            for (int mi = 0; mi < 4; mi++)
                #pragma unroll
                for (int ni = 0; ni < 4; ni++)
                    MMA_OP(acc[mi][ni], A0[mi], A1[mi], A2[mi], A3[mi], B0[ni], B1[ni]);
        }
    }

    // ---------------- epilogue ----------------
    const int em = (lane >> 2);
    const int en = (lane & 3) * 2;
    // EPI==2: segment is uniform per CTA (128 | 256)
    const int seg = m0 >> 8;
    __nv_bfloat16* Oseg = (EPI == 2) ? (seg == 0 ? O0 : (seg == 1 ? O1 : O2)) : O0;
    const float segscale = (EPI == 2) ? (seg == 0 ? QSCALE : 1.0f) : scale;

    #pragma unroll
    for (int mi = 0; mi < 4; mi++) {
        const int mA = m0 + wm*64 + mi*16 + em;
        const int mB = mA + 8;
        #pragma unroll
        for (int ni = 0; ni < 4; ni++) {
            const int n = n0 + wn*32 + ni*8 + en;
            float* d = acc[mi][ni];
            if (EPI == 0) {
                const float bvA = bias[mA], bvB = bias[mB];
                float2 oA = { (d[0] + bvA)*scale, (d[1] + bvA)*scale };
                float2 oB = { (d[2] + bvB)*scale, (d[3] + bvB)*scale };
                float2 rA = *(const float2*)&R[(size_t)mA*ldo + n];
                float2 rB = *(const float2*)&R[(size_t)mB*ldo + n];
                oA.x += rA.x; oA.y += rA.y; oB.x += rB.x; oB.y += rB.y;
                *(float2*)&OutF[(size_t)mA*ldo + n] = oA;
                *(float2*)&OutF[(size_t)mB*ldo + n] = oB;
            } else if (EPI == 1) {
                *(__nv_bfloat162*)&O0[(size_t)mA*ldo + n] = pack_bf2(d[0]*scale, d[1]*scale);
                *(__nv_bfloat162*)&O0[(size_t)mB*ldo + n] = pack_bf2(d[2]*scale, d[3]*scale);
            } else {
                const float bvA = bias[mA], bvB = bias[mB];
                const int rA = mA & 255, rB = mB & 255;
                *(__nv_bfloat162*)&Oseg[(size_t)rA*ldo + n] =
                    pack_bf2((d[0] + bvA)*segscale, (d[1] + bvA)*segscale);
                *(__nv_bfloat162*)&Oseg[(size_t)rB*ldo + n] =
                    pack_bf2((d[2] + bvB)*segscale, (d[3] + bvB)*segscale);
            }
        }
    }
}

// ---------------- prep: stack + convert weights/biases ----------------
__global__ void prep_kernel(const float* __restrict__ wq, const float* __restrict__ wk,
                            const float* __restrict__ wv, const float* __restrict__ wp,
                            const float* __restrict__ bq, const float* __restrict__ bk,
                            const float* __restrict__ bv) {
    int i = blockIdx.x * 256 + threadIdx.x;
    if (i < 3*CH*CH) {
        int r = i / CH;
        int seg = r >> 8;
        const float* w = seg == 0 ? wq : (seg == 1 ? wk : wv);
        g_wb[i] = __float2bfloat16(w[(size_t)(r & 255)*CH + (i % CH)]);
    } else if (i < 4*CH*CH) {
        int j = i - 3*CH*CH;
        g_wpb[j] = __float2bfloat16(wp[j]);
    } else if (i < 4*CH*CH + 3*CH) {
        int j = i - 4*CH*CH;
        int seg = j >> 8;
        const float* bb = seg == 0 ? bq : (seg == 1 ? bk : bv);
        g_bias[j] = bb[j & 255];
    }
}

// ---------------- GroupNorm -> bf16 h ----------------
__global__ void groupnorm_kernel(const float* __restrict__ x,
                                 const float* __restrict__ gamma,
                                 const float* __restrict__ beta) {
    int bg = blockIdx.x;
    int b  = bg / NGRP;
    int g  = bg % NGRP;
    const size_t base = ((size_t)b*CH + (size_t)g*CPG) * NPIX;
    const float4* xp4 = (const float4*)(x + base);
    const int tid = threadIdx.x;
    const int NV = CPG*NPIX/4;

    float s = 0.f, s2 = 0.f;
    for (int i = tid; i < NV; i += 256) {
        float4 v = xp4[i];
        s  += v.x + v.y + v.z + v.w;
        s2 += v.x*v.x + v.y*v.y + v.z*v.z + v.w*v.w;
    }
    __shared__ float sh[256], sh2[256];
    sh[tid] = s; sh2[tid] = s2;
    __syncthreads();
    for (int o = 128; o > 0; o >>= 1) {
        if (tid < o) { sh[tid] += sh[tid+o]; sh2[tid] += sh2[tid+o]; }
        __syncthreads();
    }
    float inv_n = 1.0f / (float)(CPG*NPIX);
    float mean  = sh[0] * inv_n;
    float var   = sh2[0] * inv_n - mean*mean;
    float rstd  = rsqrtf(var + GN_EPS);

    __nv_bfloat162* hb2 = (__nv_bfloat162*)(g_hb + base);
    for (int i = tid; i < NV; i += 256) {
        int ch = g*CPG + (i*4) / NPIX;
        float ga = gamma[ch] * rstd;
        float be = beta[ch] - mean * ga;
        float4 v = xp4[i];
        hb2[i*2]   = pack_bf2(v.x*ga + be, v.y*ga + be);
        hb2[i*2+1] = pack_bf2(v.z*ga + be, v.w*ga + be);
    }
}

// ---------------- softmax over keys, in-place bf16 ----------------
__global__ void softmax_kernel() {
    const size_t row = (size_t)blockIdx.x;
    __nv_bfloat162* p2 = (__nv_bfloat162*)(g_sb + row * NPIX);
    const int tid = threadIdx.x;

    float v[16];
    float mx = -INFINITY;
    #pragma unroll
    for (int s = 0; s < 8; s++) {
        __nv_bfloat162 t = p2[tid + 256*s];
        v[2*s]   = __bfloat162float(t.x);
        v[2*s+1] = __bfloat162float(t.y);
        mx = fmaxf(mx, fmaxf(v[2*s], v[2*s+1]));
    }
    __shared__ float sh[256];
    sh[tid] = mx; __syncthreads();
    for (int o = 128; o > 0; o >>= 1) {
        if (tid < o) sh[tid] = fmaxf(sh[tid], sh[tid+o]);
        __syncthreads();
    }
    mx = sh[0];
    __syncthreads();

    float sum = 0.f;
    #pragma unroll
    for (int s = 0; s < 16; s++) {
        v[s] = __expf(v[s] - mx);
        sum += v[s];
    }
    sh[tid] = sum; __syncthreads();
    for (int o = 128; o > 0; o >>= 1) {
        if (tid < o) sh[tid] += sh[tid+o];
        __syncthreads();
    }
    float inv = 1.0f / sh[0];
    #pragma unroll
    for (int s = 0; s < 8; s++)
        p2[tid + 256*s] = pack_bf2(v[2*s]*inv, v[2*s+1]*inv);
}

// ---------------- launch ----------------
extern "C" void kernel_launch(void* const* d_in, const int* in_sizes, int n_in,
                              void* d_out, int out_size) {
    const float* x     = (const float*)d_in[0];
    const float* gamma = (const float*)d_in[1];
    const float* beta  = (const float*)d_in[2];
    const float* wq = (const float*)d_in[3];
    const float* bq = (const float*)d_in[4];
    const float* wk = (const float*)d_in[5];
    const float* bk = (const float*)d_in[6];
    const float* wv = (const float*)d_in[7];
    const float* bv = (const float*)d_in[8];
    const float* wp = (const float*)d_in[9];
    const float* bp = (const float*)d_in[10];
    float* out = (float*)d_out;

    __nv_bfloat16 *p_sb, *p_hb, *p_qb, *p_kb, *p_vb, *p_ob, *p_wb, *p_wpb;
    float* p_bias;
    cudaGetSymbolAddress((void**)&p_sb,  g_sb);
    cudaGetSymbolAddress((void**)&p_hb,  g_hb);
    cudaGetSymbolAddress((void**)&p_qb,  g_qb);
    cudaGetSymbolAddress((void**)&p_kb,  g_kb);
    cudaGetSymbolAddress((void**)&p_vb,  g_vb);
    cudaGetSymbolAddress((void**)&p_ob,  g_ob);
    cudaGetSymbolAddress((void**)&p_wb,  g_wb);
    cudaGetSymbolAddress((void**)&p_wpb, g_wpb);
    cudaGetSymbolAddress((void**)&p_bias, g_bias);

    // smem sizes: plain=128*80=10240, trans=32*272=8704
    const int SM_QKV = 2 * (10240 + 8704);   // A plain, B trans, 2 stages = 37888
    const int SM_SCO = 2 * (8704 + 8704);    // both trans, 2 stages       = 34816
    const int SM_PV  = 4 * (10240 + 10240);  // both plain, 4 stages       = 81920
    cudaFuncSetAttribute(mma_gemm<0,1,2,2>, cudaFuncAttributeMaxDynamicSharedMemorySize, SM_QKV);
    cudaFuncSetAttribute(mma_gemm<1,1,1,2>, cudaFuncAttributeMaxDynamicSharedMemorySize, SM_SCO);
    cudaFuncSetAttribute(mma_gemm<0,0,1,4>, cudaFuncAttributeMaxDynamicSharedMemorySize, SM_PV);
    cudaFuncSetAttribute(mma_gemm<0,1,0,2>, cudaFuncAttributeMaxDynamicSharedMemorySize, SM_QKV);

    const size_t sCN = (size_t)CH * NPIX;
    const size_t sNN = (size_t)NPIX * NPIX;

    // 0. prep weights/biases
    prep_kernel<<<(4*CH*CH + 3*CH + 255)/256, 256>>>(wq, wk, wv, wp, bq, bk, bv);

    // 1. GroupNorm -> bf16 h
    groupnorm_kernel<<<BATCH*NGRP, 256>>>(x, gamma, beta);

    // 2. fused qkv: A = stacked W [768][256] plain, B = h [c][n] trans
    //    out routed to q/k/v (c,n) bf16; q pre-scaled by C^-0.5
    dim3 gqkv(NPIX/128, (3*CH)/128, BATCH);
    mma_gemm<0,1,2,2><<<gqkv, 256, SM_QKV>>>(
        p_wb, p_hb, p_bias, nullptr, p_qb, p_kb, p_vb,
        nullptr, 1.0f, CH, CH, NPIX, NPIX, 0, sCN, sCN);

    // 3. scores[i][j] = q[c][i].k[c][j] (already scaled): both trans, K=256
    dim3 gsc(NPIX/128, NPIX/128, BATCH);
    mma_gemm<1,1,1,2><<<gsc, 256, SM_SCO>>>(
        p_qb, p_kb, nullptr, nullptr, p_sb, nullptr, nullptr,
        nullptr, 1.0f, CH, NPIX, NPIX, NPIX, sCN, sCN, sNN);

    // 4. softmax in-place (bf16)
    softmax_kernel<<<BATCH*NPIX, 256>>>();

    // 5. o[c][i] = sum_j v[c][j]*attn[i][j]: both plain, K=4096
    dim3 gpv(NPIX/128, CH/128, BATCH);
    mma_gemm<0,0,1,4><<<gpv, 256, SM_PV>>>(
        p_vb, p_sb, nullptr, nullptr, p_ob, nullptr, nullptr,
        nullptr, 1.0f, NPIX, NPIX, NPIX, NPIX, sCN, sNN, sCN);

    // 6. proj: A = Wp plain, B = o trans; fp32 out + bias + residual
    mma_gemm<0,1,0,2><<<gpv, 256, SM_QKV>>>(
        p_wpb, p_ob, bp, out, nullptr, nullptr, nullptr,
        x, 1.0f, CH, CH, NPIX, NPIX, 0, sCN, sCN);
}